// round 2
// baseline (speedup 1.0000x reference)
#include <cuda_runtime.h>
#include <cuda_bf16.h>
#include <cstdint>

// GramsEmbedding: out[b,s,:] = sum over the SET {idx[0,b,s], idx[1,b,s]} of weight rows.
// (n_hot uses max/union semantics: duplicate grams collapse, so equal indices
// contribute the row only once.)
//
// Shapes: input int32 [2, 2, 1024]  (K, B, S) -> 2048 positions per gram
//         weight f32  [32000, 128]
//         out    f32  [2, 1024, 128]
//
// One warp per (b,s) position; each lane handles a float4 (4 dims) of the
// 128-dim embedding. Fully coalesced 128B-per-warp loads/stores.

static constexpr int NUM_POS   = 2 * 1024;   // B*S
static constexpr int EMBED_DIM = 128;

__global__ void grams_embedding_kernel(const int* __restrict__ idx,
                                       const float* __restrict__ weight,
                                       float* __restrict__ out) {
    const int gwarp = (blockIdx.x * blockDim.x + threadIdx.x) >> 5;
    const int lane  = threadIdx.x & 31;
    if (gwarp >= NUM_POS) return;

    const int i0 = __ldg(&idx[gwarp]);            // gram 0, position gwarp
    const int i1 = __ldg(&idx[NUM_POS + gwarp]);  // gram 1, position gwarp

    const float4* w0 = reinterpret_cast<const float4*>(weight + (size_t)i0 * EMBED_DIM);
    float4 v = __ldg(&w0[lane]);

    if (i1 != i0) {
        const float4* w1 = reinterpret_cast<const float4*>(weight + (size_t)i1 * EMBED_DIM);
        float4 u = __ldg(&w1[lane]);
        v.x += u.x; v.y += u.y; v.z += u.z; v.w += u.w;
    }

    reinterpret_cast<float4*>(out + (size_t)gwarp * EMBED_DIM)[lane] = v;
}

extern "C" void kernel_launch(void* const* d_in, const int* in_sizes, int n_in,
                              void* d_out, int out_size) {
    const int*   idx    = (const int*)d_in[0];    // [2, 2, 1024] int32
    const float* weight = (const float*)d_in[1];  // [32000, 128] f32
    float*       out    = (float*)d_out;          // [2, 1024, 128] f32

    // 2048 warps total; 256 threads (8 warps) per block -> 256 blocks
    // (>=1 CTA per SM on 148 SMs; ~14 warps/SM for memory-latency hiding).
    const int threads = 256;
    const int warps_per_block = threads / 32;
    const int blocks = (NUM_POS + warps_per_block - 1) / warps_per_block;
    grams_embedding_kernel<<<blocks, threads>>>(idx, weight, out);
}

// round 7
// speedup vs baseline: 1.0147x; 1.0147x over previous
#include <cuda_runtime.h>
#include <cuda_bf16.h>
#include <cstdint>

// GramsEmbedding: out[b,s,:] = union-sum of weight rows {idx[0,b,s], idx[1,b,s]}.
// Duplicate indices contribute once (n_hot max semantics).
//
// input  int32 [2, 2, 1024]  -> i0 = idx[pos], i1 = idx[2048 + pos]
// weight f32   [32000, 128]
// out    f32   [2, 1024, 128]
//
// Latency-bound kernel (ncu: DRAM 5%, issue 3.6%). Strategy: 4 positions per
// warp; one coalesced idx round-trip (8 lanes), then 8 independent LDG.128
// weight loads in flight per warp before any dependent math.

static constexpr int NUM_POS      = 2 * 1024;  // B*S
static constexpr int EMBED_DIM    = 128;
static constexpr int POS_PER_WARP = 4;

__global__ void grams_embedding_kernel(const int* __restrict__ idx,
                                       const float* __restrict__ weight,
                                       float* __restrict__ out) {
    const int warp = (blockIdx.x * blockDim.x + threadIdx.x) >> 5;
    const int lane = threadIdx.x & 31;
    const int base = warp * POS_PER_WARP;
    if (base >= NUM_POS) return;

    // One coalesced idx fetch: lanes 0..3 load i0 for positions base..base+3,
    // lanes 4..7 load i1 for the same positions. Single memory round trip.
    int my = 0;
    if (lane < 2 * POS_PER_WARP) {
        const int p = base + (lane & (POS_PER_WARP - 1));
        my = __ldg(&idx[(lane >> 2) * NUM_POS + p]);
    }

    int i0[POS_PER_WARP], i1[POS_PER_WARP];
#pragma unroll
    for (int j = 0; j < POS_PER_WARP; j++) {
        i0[j] = __shfl_sync(0xFFFFFFFFu, my, j);
        i1[j] = __shfl_sync(0xFFFFFFFFu, my, POS_PER_WARP + j);
    }

    // Issue all 8 row loads back-to-back (independent -> MLP=8 per warp).
    float4 v[POS_PER_WARP], u[POS_PER_WARP];
#pragma unroll
    for (int j = 0; j < POS_PER_WARP; j++)
        v[j] = __ldg(reinterpret_cast<const float4*>(weight + (size_t)i0[j] * EMBED_DIM) + lane);
#pragma unroll
    for (int j = 0; j < POS_PER_WARP; j++)
        u[j] = __ldg(reinterpret_cast<const float4*>(weight + (size_t)i1[j] * EMBED_DIM) + lane);

#pragma unroll
    for (int j = 0; j < POS_PER_WARP; j++) {
        const float s = (i0[j] != i1[j]) ? 1.0f : 0.0f;  // branchless dup-collapse
        float4 r = v[j];
        r.x = fmaf(s, u[j].x, r.x);
        r.y = fmaf(s, u[j].y, r.y);
        r.z = fmaf(s, u[j].z, r.z);
        r.w = fmaf(s, u[j].w, r.w);
        reinterpret_cast<float4*>(out + (size_t)(base + j) * EMBED_DIM)[lane] = r;
    }
}

extern "C" void kernel_launch(void* const* d_in, const int* in_sizes, int n_in,
                              void* d_out, int out_size) {
    const int*   idx    = (const int*)d_in[0];    // [2, 2, 1024] int32
    const float* weight = (const float*)d_in[1];  // [32000, 128] f32
    float*       out    = (float*)d_out;          // [2, 1024, 128] f32

    // 512 warps total (4 positions each); 64-thread CTAs -> 256 CTAs so all
    // 148 SMs get work.
    const int threads = 64;
    const int warps_per_block = threads / 32;
    const int blocks = NUM_POS / (POS_PER_WARP * warps_per_block);
    grams_embedding_kernel<<<blocks, threads>>>(idx, weight, out);
}